// round 4
// baseline (speedup 1.0000x reference)
#include <cuda_runtime.h>
#include <cuda_bf16.h>
#include <cstdint>

// ---------------- problem constants ----------------
#define BATCH    64
#define INCH     8192
#define OUTCH    8192
#define NT       64             // out-channel tile per CTA
#define KT       64             // K tile (64 bf16 = 128B row)
#define NITER    (INCH / KT)    // 128
#define NTHREADS 256
#define NCTAS    (OUTCH / NT)   // 128
#define NSTAGE   3

// per stage: A 128x128B = 16KB, B 64x128B = 8KB
#define STAGE_BYTES 24576
#define SMEM_BYTES  (NSTAGE * STAGE_BYTES)   // 73728

__device__ __nv_bfloat16 g_xsplit[(size_t)2 * BATCH * INCH]; // rows 0..63 hi, 64..127 lo
__device__ float g_abssum;

// ---------------- helpers ----------------
__device__ __forceinline__ uint32_t smem_u32(const void* p) {
    uint32_t a;
    asm("{ .reg .u64 t; cvta.to.shared.u64 t, %1; cvt.u32.u64 %0, t; }" : "=r"(a) : "l"(p));
    return a;
}

#define SW128(off) ((off) ^ (((off) >> 3) & 0x70))

__device__ __forceinline__ uint32_t sgn_bf16(float w) {
    uint32_t u = __float_as_uint(w);
    return (w == 0.0f) ? 0u : (0x3F80u | ((u >> 16) & 0x8000u));
}

__device__ __forceinline__ void ldsm_x4(uint32_t* r, uint32_t addr) {
    asm volatile("ldmatrix.sync.aligned.m8n8.x4.shared.b16 {%0,%1,%2,%3}, [%4];"
                 : "=r"(r[0]), "=r"(r[1]), "=r"(r[2]), "=r"(r[3]) : "r"(addr));
}

__device__ __forceinline__ void mma_bf16(float* c, const uint32_t* a, const uint32_t* b) {
    asm volatile(
        "mma.sync.aligned.m16n8k16.row.col.f32.bf16.bf16.f32 "
        "{%0,%1,%2,%3}, {%4,%5,%6,%7}, {%8,%9}, {%0,%1,%2,%3};"
        : "+f"(c[0]), "+f"(c[1]), "+f"(c[2]), "+f"(c[3])
        : "r"(a[0]), "r"(a[1]), "r"(a[2]), "r"(a[3]), "r"(b[0]), "r"(b[1]));
}

__device__ __forceinline__ void cp_async16(uint32_t dst, const void* src) {
    asm volatile("cp.async.cg.shared.global [%0], [%1], 16;"
                 :: "r"(dst), "l"(__cvta_generic_to_global(src)) : "memory");
}
#define CP_COMMIT() asm volatile("cp.async.commit_group;" ::: "memory")
#define CP_WAIT0()  asm volatile("cp.async.wait_group 0;" ::: "memory")
#define CP_WAIT1()  asm volatile("cp.async.wait_group 1;" ::: "memory")

// ---------------- kernel 0: split x into bf16 hi/lo planes (vectorized) ----------------
__global__ void hb_split_kernel(const float* __restrict__ x) {
    int i = blockIdx.x * blockDim.x + threadIdx.x;   // over float4 chunks (131072)
    if (i == 0) g_abssum = 0.0f;
    float4 v = reinterpret_cast<const float4*>(x)[i];

    __nv_bfloat16 h0 = __float2bfloat16(v.x), h1 = __float2bfloat16(v.y);
    __nv_bfloat16 h2 = __float2bfloat16(v.z), h3 = __float2bfloat16(v.w);
    __nv_bfloat16 l0 = __float2bfloat16(v.x - __bfloat162float(h0));
    __nv_bfloat16 l1 = __float2bfloat16(v.y - __bfloat162float(h1));
    __nv_bfloat16 l2 = __float2bfloat16(v.z - __bfloat162float(h2));
    __nv_bfloat16 l3 = __float2bfloat16(v.w - __bfloat162float(h3));

    __nv_bfloat162* hp = reinterpret_cast<__nv_bfloat162*>(g_xsplit);
    __nv_bfloat162* lp = hp + (BATCH * INCH / 2);
    hp[i * 2 + 0] = __nv_bfloat162(h0, h1);
    hp[i * 2 + 1] = __nv_bfloat162(h2, h3);
    lp[i * 2 + 0] = __nv_bfloat162(l0, l1);
    lp[i * 2 + 1] = __nv_bfloat162(l2, l3);
}

// ---------------- kernel 1: fused sign + mma.sync GEMM + |W| reduce ----------------
__global__ void __launch_bounds__(NTHREADS, 1)
hb_gemm_kernel(const float* __restrict__ W, float* __restrict__ out) {
    extern __shared__ __align__(1024) char smem[];
    const uint32_t sb = smem_u32(smem);

    const int tid  = threadIdx.x;
    const int lane = tid & 31;
    const int wid  = tid >> 5;
    const int wm   = wid & 3;          // 4 warps along M
    const int wn   = wid >> 2;         // 2 warps along N
    const int n0   = blockIdx.x * NT;
    const int nw   = wn * 32;          // warp's n offset within CTA tile
    const int mhi  = wm * 16;          // hi-plane rows
    const int mlo  = 64 + wm * 16;     // lo-plane rows

#define A_OFF(s) (sb + (uint32_t)(s) * STAGE_BYTES)
#define B_OFF(s) (sb + (uint32_t)(s) * STAGE_BYTES + 16384)

    float c[2][4][4];                  // [plane][n-tile][frag]
#pragma unroll
    for (int p = 0; p < 2; p++)
#pragma unroll
        for (int nt = 0; nt < 4; nt++)
#pragma unroll
            for (int r = 0; r < 4; r++) c[p][nt][r] = 0.0f;

    float absacc = 0.0f;
    float4 wv[4];   // 16 staged W floats

    // ldmatrix per-lane coordinates (verified layout from R3)
    const int arow  = lane & 15;
    const int ac8   = lane >> 4;
    const int brow0 = nw +      (lane & 7) + ((lane >> 4) << 3);
    const int brow1 = nw + 16 + (lane & 7) + ((lane >> 4) << 3);
    const int bc8   = (lane >> 3) & 1;

    // W load/store coords: 2 groups of 8 contiguous floats per thread
    int wrow[2], wkc[2];
#pragma unroll
    for (int g = 0; g < 2; g++) { int cid = tid + g * NTHREADS; wrow[g] = cid >> 3; wkc[g] = cid & 7; }
    // A cp.async coords: 4 groups of 16B per thread
    int xrow[4], xc8[4];
#pragma unroll
    for (int g = 0; g < 4; g++) { int cid = tid + g * NTHREADS; xrow[g] = cid >> 3; xc8[g] = cid & 7; }

#define LOADW(it) do { \
    int _k0 = (it) * KT; \
    _Pragma("unroll") \
    for (int g = 0; g < 2; g++) { \
        const float4* p = reinterpret_cast<const float4*>( \
            W + (size_t)(n0 + wrow[g]) * INCH + _k0 + wkc[g] * 8); \
        wv[2*g]   = p[0]; \
        wv[2*g+1] = p[1]; \
    } \
} while (0)

#define CPA(it, st) do { \
    int _k0 = (it) * KT; \
    _Pragma("unroll") \
    for (int g = 0; g < 4; g++) { \
        const __nv_bfloat16* src = g_xsplit + (size_t)xrow[g] * INCH + _k0 + xc8[g] * 8; \
        cp_async16(A_OFF(st) + SW128((uint32_t)(xrow[g] * 128 + xc8[g] * 16)), src); \
    } \
    CP_COMMIT(); \
} while (0)

#define STSW(st) do { \
    _Pragma("unroll") \
    for (int g = 0; g < 2; g++) { \
        float f0 = wv[2*g].x, f1 = wv[2*g].y, f2 = wv[2*g].z, f3 = wv[2*g].w; \
        float f4 = wv[2*g+1].x, f5 = wv[2*g+1].y, f6 = wv[2*g+1].z, f7 = wv[2*g+1].w; \
        absacc += fabsf(f0)+fabsf(f1)+fabsf(f2)+fabsf(f3)+fabsf(f4)+fabsf(f5)+fabsf(f6)+fabsf(f7); \
        uint32_t p0 = sgn_bf16(f0) | (sgn_bf16(f1) << 16); \
        uint32_t p1 = sgn_bf16(f2) | (sgn_bf16(f3) << 16); \
        uint32_t p2 = sgn_bf16(f4) | (sgn_bf16(f5) << 16); \
        uint32_t p3 = sgn_bf16(f6) | (sgn_bf16(f7) << 16); \
        asm volatile("st.shared.v4.b32 [%0], {%1,%2,%3,%4};" \
                     :: "r"(B_OFF(st) + SW128((uint32_t)(wrow[g] * 128 + wkc[g] * 16))), \
                        "r"(p0), "r"(p1), "r"(p2), "r"(p3) : "memory"); \
    } \
} while (0)

#define COMPUTE(st) do { \
    const uint32_t _A = A_OFF(st), _B = B_OFF(st); \
    _Pragma("unroll") \
    for (int ks = 0; ks < 4; ks++) { \
        uint32_t bf0[4], bf1[4], af0[4], af1[4]; \
        ldsm_x4(bf0, _B + SW128((uint32_t)(brow0 * 128 + ks * 32 + bc8 * 16))); \
        ldsm_x4(bf1, _B + SW128((uint32_t)(brow1 * 128 + ks * 32 + bc8 * 16))); \
        ldsm_x4(af0, _A + SW128((uint32_t)((mhi + arow) * 128 + ks * 32 + ac8 * 16))); \
        ldsm_x4(af1, _A + SW128((uint32_t)((mlo + arow) * 128 + ks * 32 + ac8 * 16))); \
        mma_bf16(c[0][0], af0, bf0); mma_bf16(c[0][1], af0, bf0 + 2); \
        mma_bf16(c[0][2], af0, bf1); mma_bf16(c[0][3], af0, bf1 + 2); \
        mma_bf16(c[1][0], af1, bf0); mma_bf16(c[1][1], af1, bf0 + 2); \
        mma_bf16(c[1][2], af1, bf1); mma_bf16(c[1][3], af1, bf1 + 2); \
    } \
} while (0)

    // ---- prologue: fill stages 0 and 1 ----
    LOADW(0); CPA(0, 0); STSW(0);
    LOADW(1); CPA(1, 1); STSW(1);
    CP_WAIT1();            // stage 0 A resident
    __syncthreads();

    // ---- main loop: one sync per iter ----
    for (int it = 0; it < NITER; ++it) {
        const int cur = it % 3;
        const int pre = (it + 2) % 3;
        if (it + 2 < NITER) { LOADW(it + 2); CPA(it + 2, pre); }
        COMPUTE(cur);
        if (it + 2 < NITER) STSW(pre);
        if (it + 1 < NITER) {
            if (it + 2 < NITER) CP_WAIT1(); else CP_WAIT0();
            __syncthreads();
        }
    }

    // |W| warp reduce + one atomic per warp
#pragma unroll
    for (int o = 16; o > 0; o >>= 1) absacc += __shfl_xor_sync(0xFFFFFFFFu, absacc, o);
    if (lane == 0) atomicAdd(&g_abssum, absacc);

    // epilogue: combine hi+lo planes in registers -> global (unscaled)
#pragma unroll
    for (int nt = 0; nt < 4; nt++) {
        int col = n0 + nw + nt * 8 + (lane & 3) * 2;
        int r0  = wm * 16 + (lane >> 2);
        float2 v0 = make_float2(c[0][nt][0] + c[1][nt][0], c[0][nt][1] + c[1][nt][1]);
        float2 v1 = make_float2(c[0][nt][2] + c[1][nt][2], c[0][nt][3] + c[1][nt][3]);
        *reinterpret_cast<float2*>(out + (size_t)r0 * OUTCH + col) = v0;
        *reinterpret_cast<float2*>(out + (size_t)(r0 + 8) * OUTCH + col) = v1;
    }

#undef LOADW
#undef CPA
#undef STSW
#undef COMPUTE
#undef A_OFF
#undef B_OFF
}

// ---------------- kernel 2: apply scale = mean(|W|) ----------------
__global__ void hb_scale_kernel(float* __restrict__ out) {
    float s = g_abssum * (1.0f / ((float)INCH * (float)OUTCH));
    int i = blockIdx.x * blockDim.x + threadIdx.x;
    float4* o = reinterpret_cast<float4*>(out);
    float4 v = o[i];
    v.x *= s; v.y *= s; v.z *= s; v.w *= s;
    o[i] = v;
}

// ---------------- launch ----------------
extern "C" void kernel_launch(void* const* d_in, const int* in_sizes, int n_in,
                              void* d_out, int out_size) {
    const float* x = (const float*)d_in[0];
    const float* w = (const float*)d_in[1];
    if (n_in >= 2 && in_sizes[0] != BATCH * INCH) { const float* t = x; x = w; w = t; }
    float* out = (float*)d_out;

    static bool attr_set = false;
    if (!attr_set) {
        cudaFuncSetAttribute(hb_gemm_kernel,
                             cudaFuncAttributeMaxDynamicSharedMemorySize, SMEM_BYTES);
        attr_set = true;
    }

    hb_split_kernel<<<(BATCH * INCH / 4) / 256, 256>>>(x);
    hb_gemm_kernel<<<NCTAS, NTHREADS, SMEM_BYTES>>>(w, out);
    hb_scale_kernel<<<(BATCH * OUTCH / 4) / 256, 256>>>(out);
}